// round 12
// baseline (speedup 1.0000x reference)
#include <cuda_runtime.h>
#include <cuda_bf16.h>
#include <cstdint>

#define S_LEN 512
#define BATCH 2048
#define DIN 64
#define HID 128
#define NROWS (S_LEN * BATCH)

// U scratch (split-packed bf16 pairs), per 16-row block bi, 16 loop-warps:
// u32 index = bi*2048 + lw*128 + lane*4 + {r0e0, r0e1, r1e0, r1e1}
__device__ uint32_t g_U[(size_t)NROWS * HID];

__device__ __forceinline__ float fast_tanh(float v) {
    float e = __expf(2.0f * v);
    return 1.0f - __fdividef(2.0f, e + 1.0f);
}
__device__ __forceinline__ void ldsm4(uint32_t r[4], uint32_t addr) {
    asm volatile("ldmatrix.sync.aligned.m8n8.x4.shared.b16 {%0,%1,%2,%3}, [%4];"
                 : "=r"(r[0]), "=r"(r[1]), "=r"(r[2]), "=r"(r[3]) : "r"(addr));
}
__device__ __forceinline__ void ldsm2(uint32_t r[2], uint32_t addr) {
    asm volatile("ldmatrix.sync.aligned.m8n8.x2.shared.b16 {%0,%1}, [%2];"
                 : "=r"(r[0]), "=r"(r[1]) : "r"(addr));
}
__device__ __forceinline__ void mma_bf16(float d[4], const uint32_t a[4],
                                         const uint32_t b0, const uint32_t b1) {
    asm volatile("mma.sync.aligned.m16n8k16.row.col.f32.bf16.bf16.f32 "
                 "{%0,%1,%2,%3}, {%4,%5,%6,%7}, {%8,%9}, {%0,%1,%2,%3};"
                 : "+f"(d[0]), "+f"(d[1]), "+f"(d[2]), "+f"(d[3])
                 : "r"(a[0]), "r"(a[1]), "r"(a[2]), "r"(a[3]), "r"(b0), "r"(b1));
}
__device__ __forceinline__ uint32_t smem_u32(const void* p) {
    uint32_t a;
    asm("{ .reg .u64 t; cvta.to.shared.u64 t, %1; cvt.u32.u64 %0, t; }"
        : "=r"(a) : "l"(p));
    return a;
}
__device__ __forceinline__ uint32_t cvt2bf(float lo, float hi) {
    uint32_t r;
    asm("cvt.rn.bf16x2.f32 %0, %1, %2;" : "=r"(r) : "f"(hi), "f"(lo));
    return r;
}
// packed split element: low16 = main bf16, high16 = residual bf16
__device__ __forceinline__ float su(uint32_t p) {
    return __uint_as_float(p << 16) + __uint_as_float(p & 0xFFFF0000u);
}
__device__ __forceinline__ void split_pair(float v0, float v1,
                                           uint32_t& hi, uint32_t& lo) {
    hi = cvt2bf(v0, v1);
    float f0 = __uint_as_float(hi << 16);
    float f1 = __uint_as_float(hi & 0xFFFF0000u);
    lo = cvt2bf(v0 - f0, v1 - f1);
}

// ============ Kernel 1: U = x @ W_ih^T + b_ih via bf16 mma ================

#define P2_THREADS 256
#define P2_GRID 592
#define NTILES (NROWS / 32)
#define PROW 144
#define PWSPL (HID * PROW)
#define PXSPL (32 * PROW)
#define PXBUF (2 * PXSPL)
#define PW 0
#define PX (2 * PWSPL)
#define P2_SMEM (PX + 2 * PXBUF)

__global__ void __launch_bounds__(P2_THREADS)
precompute_kernel(const float* __restrict__ x, const float* __restrict__ Wih,
                  const float* __restrict__ bih)
{
    extern __shared__ unsigned char sm[];
    const uint32_t smem_b = smem_u32(sm);

    const int tid  = threadIdx.x;
    const int warp = tid >> 5;
    const int lane = tid & 31;
    const int tq   = lane & 3;
    const int rg   = warp >> 2;
    const int colWp = (warp & 3) * 32;

    // ---- stage W_ih splits (once) ----
    for (int idx = tid; idx < HID * DIN; idx += P2_THREADS) {
        const int n = idx >> 6, k = idx & 63;
        float w = Wih[idx];
        __nv_bfloat16 w0 = __float2bfloat16(w);
        __nv_bfloat16 w1 = __float2bfloat16(w - __bfloat162float(w0));
        const size_t off = (size_t)n * PROW + (size_t)k * 2;
        *(__nv_bfloat16*)(sm + PW + off)         = w0;
        *(__nv_bfloat16*)(sm + PW + PWSPL + off) = w1;
    }

    float bi0[4], bi1[4];
    #pragma unroll
    for (int nt = 0; nt < 4; ++nt) {
        bi0[nt] = bih[colWp + nt * 8 + tq * 2];
        bi1[nt] = bih[colWp + nt * 8 + tq * 2 + 1];
    }

    const int q  = lane >> 3;
    const int lr = lane & 7;
    const uint32_t xa_lane = (uint32_t)((rg * 16 + lr + (q & 1) * 8) * PROW +
                                        ((q & 2) ? 8 : 0) * 2);
    const uint32_t wb = smem_b + PW +
        (uint32_t)((colWp + lr + ((q & 2) ? 8 : 0)) * PROW + ((q & 1) ? 8 : 0) * 2);

    const int sr = tid >> 3;
    const int sc = (tid & 7) * 8;

    // ---- prologue: load x for first tile ----
    int blk = blockIdx.x;
    float4 v0, v1;
    if (blk < NTILES) {
        const float* p = x + ((size_t)blk * 32 + sr) * DIN + sc;
        v0 = *(const float4*)p; v1 = *(const float4*)(p + 4);
    }
    int cur = 0;
    __syncthreads();

    while (blk < NTILES) {
        // ---- stage x tile splits: 2x STS.128 per thread ----
        {
            uint4 hi, lo;
            split_pair(v0.x, v0.y, hi.x, lo.x);
            split_pair(v0.z, v0.w, hi.y, lo.y);
            split_pair(v1.x, v1.y, hi.z, lo.z);
            split_pair(v1.z, v1.w, hi.w, lo.w);
            unsigned char* xb = sm + PX + cur * PXBUF + sr * PROW + sc * 2;
            *(uint4*)xb           = hi;
            *(uint4*)(xb + PXSPL) = lo;
        }
        __syncthreads();

        // ---- prefetch next tile ----
        const int nblk = blk + P2_GRID;
        if (nblk < NTILES) {
            const float* p = x + ((size_t)nblk * 32 + sr) * DIN + sc;
            v0 = *(const float4*)p; v1 = *(const float4*)(p + 4);
        }

        // ---- mma: 2-way splits, 3 products ----
        float D[4][4], Dc[4][4];
        #pragma unroll
        for (int nt = 0; nt < 4; ++nt) {
            D[nt][0] = bi0[nt]; D[nt][1] = bi1[nt];
            D[nt][2] = bi0[nt]; D[nt][3] = bi1[nt];
            Dc[nt][0] = Dc[nt][1] = Dc[nt][2] = Dc[nt][3] = 0.0f;
        }
        const uint32_t xa = smem_b + PX + (uint32_t)cur * PXBUF + xa_lane;
        #pragma unroll
        for (int ks = 0; ks < 4; ++ks) {
            uint32_t A0[4], A1[4];
            ldsm4(A0, xa + ks * 32);
            ldsm4(A1, xa + PXSPL + ks * 32);
            #pragma unroll
            for (int np = 0; np < 2; ++np) {
                uint32_t B0[4], B1[4];
                ldsm4(B0, wb + (uint32_t)(np * 16 * PROW) + ks * 32);
                ldsm4(B1, wb + PWSPL + (uint32_t)(np * 16 * PROW) + ks * 32);
                #pragma unroll
                for (int hf = 0; hf < 2; ++hf) {
                    const int nt = np * 2 + hf;
                    mma_bf16(D[nt],  A0, B0[2 * hf], B0[2 * hf + 1]);
                    mma_bf16(Dc[nt], A0, B1[2 * hf], B1[2 * hf + 1]);
                    mma_bf16(Dc[nt], A1, B0[2 * hf], B0[2 * hf + 1]);
                }
            }
        }

        // ---- write U: one uint4 (STG.128) per lane per nt, 16-warp layout --
        const size_t biBlk = ((size_t)blk * 32 >> 4) + rg;
        #pragma unroll
        for (int nt = 0; nt < 4; ++nt) {
            const int lw = 4 * (warp & 3) + nt;
            uint4 o;
            {
                uint32_t p, pr;
                split_pair(D[nt][0] + Dc[nt][0], D[nt][1] + Dc[nt][1], p, pr);
                o.x = __byte_perm(p, pr, 0x5410);
                o.y = __byte_perm(p, pr, 0x7632);
                split_pair(D[nt][2] + Dc[nt][2], D[nt][3] + Dc[nt][3], p, pr);
                o.z = __byte_perm(p, pr, 0x5410);
                o.w = __byte_perm(p, pr, 0x7632);
            }
            *(uint4*)&g_U[biBlk * 2048 + (size_t)lw * 128 + lane * 4] = o;
        }

        blk = nblk;
        cur ^= 1;
    }
}

// ====== Kernel 2: recurrence, 16 warps (4/SMSP), warp owns 8 cols ==========

#define ROWB 272
#define WSPL (HID * ROWB)
#define ASPL (16 * ROWB)
#define ABUF (2 * ASPL)
#define SM_W 0
#define SM_A (2 * WSPL)
#define L_SMEM (SM_A + 2 * ABUF)
#define L_THREADS 512

__global__ void __launch_bounds__(L_THREADS, 1)
loop_kernel(const float* __restrict__ h0, const float* __restrict__ bhh,
            const float* __restrict__ Whh, float* __restrict__ out)
{
    extern __shared__ unsigned char smem[];
    const uint32_t smem_b = smem_u32(smem);

    const int tid  = threadIdx.x;
    const int warp = tid >> 5;        // 0..15
    const int lane = tid & 31;
    const int g    = lane >> 2;
    const int tq   = lane & 3;
    const int bx   = blockIdx.x;
    const int rowBase = bx * 16;
    const int colW = warp * 8;        // warp's 8 output cols

    for (int idx = tid; idx < HID * HID; idx += L_THREADS) {
        const int n = idx >> 7, k = idx & 127;
        float w = Whh[idx];
        __nv_bfloat16 w0 = __float2bfloat16(w);
        __nv_bfloat16 w1 = __float2bfloat16(w - __bfloat162float(w0));
        const size_t off = (size_t)n * ROWB + (size_t)k * 2;
        *(__nv_bfloat16*)(smem + SM_W + off)        = w0;
        *(__nv_bfloat16*)(smem + SM_W + WSPL + off) = w1;
    }

    const float bh0v = bhh[colW + tq * 2];
    const float bh1v = bhh[colW + tq * 2 + 1];

    // lane-contiguous U address: 4 u32 per lane per bi
    #define UADDR(bi) ((size_t)(bi) * 2048 + (size_t)warp * 128 + lane * 4)

    // ---- h, a registers; stage a(0) splits ----
    float h[2][2], a[2][2];
    {
        uint4 u = *(const uint4*)&g_U[UADDR(bx)];
        #pragma unroll
        for (int r = 0; r < 2; ++r) {
            const int row = rowBase + g + 8 * r;
            float2 hv = *(const float2*)&h0[(size_t)row * HID + colW + tq * 2];
            h[r][0] = hv.x; h[r][1] = hv.y;
            const uint32_t ux = r ? u.z : u.x;
            const uint32_t uy = r ? u.w : u.y;
            a[r][0] = su(ux) * hv.x;
            a[r][1] = su(uy) * hv.y;
        }
    }
    #pragma unroll
    for (int r = 0; r < 2; ++r) {
        const int lrow = g + 8 * r;
        uint32_t p, pr;
        split_pair(a[r][0], a[r][1], p, pr);
        const size_t o = (size_t)lrow * ROWB + (size_t)(colW + tq * 2) * 2;
        *(uint32_t*)(smem + SM_A + o)        = p;
        *(uint32_t*)(smem + SM_A + ASPL + o) = pr;
    }

    // ---- 2-deep U prefetch ----
    uint4 Ua = *(const uint4*)&g_U[UADDR(128 + bx)];
    uint4 Ub = *(const uint4*)&g_U[UADDR(256 + bx)];
    __syncthreads();

    const int q  = lane >> 3;
    const int lr = lane & 7;
    const uint32_t a_off = (uint32_t)((lr + (q & 1) * 8) * ROWB + ((q & 2) ? 8 : 0) * 2);
    // B ldsm.x2 address (lanes 0..15 meaningful): row colW+(lane&7), k-half by bit3
    const uint32_t b2_off = smem_b + SM_W +
        (uint32_t)((colW + (lane & 7)) * ROWB + ((lane >> 3) & 1) * 16);

    // ---- preload W_hh B-fragments: 8 ks x 2 splits x 2 regs = 32 regs ----
    uint32_t Bf0[8][2], Bf1[8][2];
    #pragma unroll
    for (int ks = 0; ks < 8; ++ks) {
        ldsm2(Bf0[ks], b2_off + ks * 32);
        ldsm2(Bf1[ks], b2_off + WSPL + ks * 32);
    }

    const uint32_t abase = smem_b + SM_A;

    for (int t = 0; t < S_LEN; ++t) {
        const int buf = t & 1;

        // ---- hoisted U(t+1) unpack ----
        float Uf[2][2];
        Uf[0][0] = su(Ua.x); Uf[0][1] = su(Ua.y);
        Uf[1][0] = su(Ua.z); Uf[1][1] = su(Ua.w);

        // ---- mma: 3 products x 2 ks-parities = 6 chains of depth 4 ----
        float D0[2][4], D1[2][4], D2[2][4];
        D0[0][0] = bh0v; D0[0][1] = bh1v; D0[0][2] = bh0v; D0[0][3] = bh1v;
        #pragma unroll
        for (int e = 0; e < 4; ++e) {
            D0[1][e] = 0.0f;
            D1[0][e] = 0.0f; D1[1][e] = 0.0f;
            D2[0][e] = 0.0f; D2[1][e] = 0.0f;
        }

        const uint32_t abuf = abase + (uint32_t)buf * ABUF + a_off;
        #pragma unroll
        for (int ks = 0; ks < 8; ++ks) {
            const int par = ks & 1;
            uint32_t A0[4], A1[4];
            ldsm4(A0, abuf + ks * 32);
            ldsm4(A1, abuf + ASPL + ks * 32);
            mma_bf16(D0[par], A0, Bf0[ks][0], Bf0[ks][1]);
            mma_bf16(D1[par], A0, Bf1[ks][0], Bf1[ks][1]);
            mma_bf16(D2[par], A1, Bf0[ks][0], Bf0[ks][1]);
        }

        // ---- epilogue ----
        #pragma unroll
        for (int r = 0; r < 2; ++r) {
            const int lrow = g + 8 * r;
            float P0 = (D0[0][2 * r]     + D0[1][2 * r]) +
                       (D1[0][2 * r]     + D1[1][2 * r]) +
                       (D2[0][2 * r]     + D2[1][2 * r]);
            float P1 = (D0[0][2 * r + 1] + D0[1][2 * r + 1]) +
                       (D1[0][2 * r + 1] + D1[1][2 * r + 1]) +
                       (D2[0][2 * r + 1] + D2[1][2 * r + 1]);
            float h0n = fast_tanh(fmaf(P0, h[r][0], a[r][0]));
            float h1n = fast_tanh(fmaf(P1, h[r][1], a[r][1]));
            h[r][0] = h0n; h[r][1] = h1n;
            float v0 = Uf[r][0] * h0n;
            float v1 = Uf[r][1] * h1n;
            a[r][0] = v0; a[r][1] = v1;

            uint32_t p, pr;
            split_pair(v0, v1, p, pr);
            const size_t o = (size_t)(buf ^ 1) * ABUF + (size_t)lrow * ROWB +
                             (size_t)(colW + tq * 2) * 2;
            *(uint32_t*)(smem + SM_A + o)        = p;
            *(uint32_t*)(smem + SM_A + ASPL + o) = pr;
        }

        // ---- shift prefetch: Ua <- Ub, issue Ub = U(t+3) ----
        {
            const int tn = (t + 3 < S_LEN) ? t + 3 : S_LEN - 1;
            Ua = Ub;
            Ub = *(const uint4*)&g_U[UADDR(tn * 128 + bx)];
        }
        __syncthreads();
    }

    #pragma unroll
    for (int r = 0; r < 2; ++r) {
        const int row = rowBase + g + 8 * r;
        *(float2*)&out[(size_t)row * HID + colW + tq * 2] =
            make_float2(h[r][0], h[r][1]);
    }
}

// ============================== launch =====================================

extern "C" void kernel_launch(void* const* d_in, const int* in_sizes, int n_in,
                              void* d_out, int out_size)
{
    const float* x   = (const float*)d_in[0];
    const float* h0  = (const float*)d_in[1];
    const float* Wih = (const float*)d_in[2];
    const float* bih = (const float*)d_in[3];
    const float* Whh = (const float*)d_in[4];
    const float* bhh = (const float*)d_in[5];

    cudaFuncSetAttribute(precompute_kernel,
                         cudaFuncAttributeMaxDynamicSharedMemorySize, P2_SMEM);
    precompute_kernel<<<P2_GRID, P2_THREADS, P2_SMEM>>>(x, Wih, bih);

    cudaFuncSetAttribute(loop_kernel,
                         cudaFuncAttributeMaxDynamicSharedMemorySize, L_SMEM);
    loop_kernel<<<BATCH / 16, L_THREADS, L_SMEM>>>(h0, bhh, Whh, (float*)d_out);
}

// round 13
// speedup vs baseline: 1.0209x; 1.0209x over previous
#include <cuda_runtime.h>
#include <cuda_bf16.h>
#include <cstdint>

#define S_LEN 512
#define BATCH 2048
#define DIN 64
#define HID 128
#define NROWS (S_LEN * BATCH)

// U scratch (split-packed bf16 pairs), lane-contiguous fragment-major layout:
// u32 index = bi*2048 + warp*256 + lane*8 + (r*2+nt)*2 + e   (8 loop-warps)
__device__ uint32_t g_U[(size_t)NROWS * HID];

__device__ __forceinline__ float fast_tanh(float v) {
    float e = __expf(2.0f * v);
    return 1.0f - __fdividef(2.0f, e + 1.0f);
}
__device__ __forceinline__ void ldsm4(uint32_t r[4], uint32_t addr) {
    asm volatile("ldmatrix.sync.aligned.m8n8.x4.shared.b16 {%0,%1,%2,%3}, [%4];"
                 : "=r"(r[0]), "=r"(r[1]), "=r"(r[2]), "=r"(r[3]) : "r"(addr));
}
__device__ __forceinline__ void mma_bf16(float d[4], const uint32_t a[4],
                                         const uint32_t b0, const uint32_t b1) {
    asm volatile("mma.sync.aligned.m16n8k16.row.col.f32.bf16.bf16.f32 "
                 "{%0,%1,%2,%3}, {%4,%5,%6,%7}, {%8,%9}, {%0,%1,%2,%3};"
                 : "+f"(d[0]), "+f"(d[1]), "+f"(d[2]), "+f"(d[3])
                 : "r"(a[0]), "r"(a[1]), "r"(a[2]), "r"(a[3]), "r"(b0), "r"(b1));
}
__device__ __forceinline__ uint32_t smem_u32(const void* p) {
    uint32_t a;
    asm("{ .reg .u64 t; cvta.to.shared.u64 t, %1; cvt.u32.u64 %0, t; }"
        : "=r"(a) : "l"(p));
    return a;
}
__device__ __forceinline__ uint32_t cvt2bf(float lo, float hi) {
    uint32_t r;
    asm("cvt.rn.bf16x2.f32 %0, %1, %2;" : "=r"(r) : "f"(hi), "f"(lo));
    return r;
}
// packed split element: low16 = main bf16, high16 = residual bf16
__device__ __forceinline__ float su(uint32_t p) {
    return __uint_as_float(p << 16) + __uint_as_float(p & 0xFFFF0000u);
}
// round-to-nearest split (used in precompute; measured-good path)
__device__ __forceinline__ void split_pair(float v0, float v1,
                                           uint32_t& hi, uint32_t& lo) {
    hi = cvt2bf(v0, v1);
    float f0 = __uint_as_float(hi << 16);
    float f1 = __uint_as_float(hi & 0xFFFF0000u);
    lo = cvt2bf(v0 - f0, v1 - f1);
}
// truncation split: main plane via PRMT (no cvt dependency), residual exact
__device__ __forceinline__ void split_pair_t(float v0, float v1,
                                             uint32_t& hi, uint32_t& lo) {
    const uint32_t b0 = __float_as_uint(v0), b1 = __float_as_uint(v1);
    hi = __byte_perm(b0, b1, 0x7632);            // {b0>>16, b1>>16}
    float r0 = v0 - __uint_as_float(b0 & 0xFFFF0000u);
    float r1 = v1 - __uint_as_float(b1 & 0xFFFF0000u);
    lo = cvt2bf(r0, r1);
}

// ============ Kernel 1: U = x @ W_ih^T + b_ih via bf16 mma ================

#define P2_THREADS 256
#define P2_GRID 592
#define NTILES (NROWS / 32)
#define PROW 144
#define PWSPL (HID * PROW)
#define PXSPL (32 * PROW)
#define PXBUF (2 * PXSPL)
#define PW 0
#define PX (2 * PWSPL)
#define P2_SMEM (PX + 2 * PXBUF)

__global__ void __launch_bounds__(P2_THREADS)
precompute_kernel(const float* __restrict__ x, const float* __restrict__ Wih,
                  const float* __restrict__ bih)
{
    extern __shared__ unsigned char sm[];
    const uint32_t smem_b = smem_u32(sm);

    const int tid  = threadIdx.x;
    const int warp = tid >> 5;
    const int lane = tid & 31;
    const int tq   = lane & 3;
    const int rg   = warp >> 2;
    const int colWp = (warp & 3) * 32;

    // ---- stage W_ih splits (once) ----
    for (int idx = tid; idx < HID * DIN; idx += P2_THREADS) {
        const int n = idx >> 6, k = idx & 63;
        float w = Wih[idx];
        __nv_bfloat16 w0 = __float2bfloat16(w);
        __nv_bfloat16 w1 = __float2bfloat16(w - __bfloat162float(w0));
        const size_t off = (size_t)n * PROW + (size_t)k * 2;
        *(__nv_bfloat16*)(sm + PW + off)         = w0;
        *(__nv_bfloat16*)(sm + PW + PWSPL + off) = w1;
    }

    float bi0[4], bi1[4];
    #pragma unroll
    for (int nt = 0; nt < 4; ++nt) {
        bi0[nt] = bih[colWp + nt * 8 + tq * 2];
        bi1[nt] = bih[colWp + nt * 8 + tq * 2 + 1];
    }

    const int q  = lane >> 3;
    const int lr = lane & 7;
    const uint32_t xa_lane = (uint32_t)((rg * 16 + lr + (q & 1) * 8) * PROW +
                                        ((q & 2) ? 8 : 0) * 2);
    const uint32_t wb = smem_b + PW +
        (uint32_t)((colWp + lr + ((q & 2) ? 8 : 0)) * PROW + ((q & 1) ? 8 : 0) * 2);

    const int sr = tid >> 3;
    const int sc = (tid & 7) * 8;

    // ---- prologue: load x for first tile (single-deep prefetch) ----
    int blk = blockIdx.x;
    float4 v0, v1;
    if (blk < NTILES) {
        const float* p = x + ((size_t)blk * 32 + sr) * DIN + sc;
        v0 = *(const float4*)p; v1 = *(const float4*)(p + 4);
    }
    int cur = 0;
    __syncthreads();

    while (blk < NTILES) {
        // ---- stage x tile splits: 2x STS.128 per thread ----
        {
            uint4 hi, lo;
            split_pair(v0.x, v0.y, hi.x, lo.x);
            split_pair(v0.z, v0.w, hi.y, lo.y);
            split_pair(v1.x, v1.y, hi.z, lo.z);
            split_pair(v1.z, v1.w, hi.w, lo.w);
            unsigned char* xb = sm + PX + cur * PXBUF + sr * PROW + sc * 2;
            *(uint4*)xb           = hi;
            *(uint4*)(xb + PXSPL) = lo;
        }
        __syncthreads();

        // ---- prefetch next tile ----
        const int nblk = blk + P2_GRID;
        if (nblk < NTILES) {
            const float* p = x + ((size_t)nblk * 32 + sr) * DIN + sc;
            v0 = *(const float4*)p; v1 = *(const float4*)(p + 4);
        }

        // ---- mma: 2-way splits, 3 products ----
        float D[4][4], Dc[4][4];
        #pragma unroll
        for (int nt = 0; nt < 4; ++nt) {
            D[nt][0] = bi0[nt]; D[nt][1] = bi1[nt];
            D[nt][2] = bi0[nt]; D[nt][3] = bi1[nt];
            Dc[nt][0] = Dc[nt][1] = Dc[nt][2] = Dc[nt][3] = 0.0f;
        }
        const uint32_t xa = smem_b + PX + (uint32_t)cur * PXBUF + xa_lane;
        #pragma unroll
        for (int ks = 0; ks < 4; ++ks) {
            uint32_t A0[4], A1[4];
            ldsm4(A0, xa + ks * 32);
            ldsm4(A1, xa + PXSPL + ks * 32);
            #pragma unroll
            for (int np = 0; np < 2; ++np) {
                uint32_t B0[4], B1[4];
                ldsm4(B0, wb + (uint32_t)(np * 16 * PROW) + ks * 32);
                ldsm4(B1, wb + PWSPL + (uint32_t)(np * 16 * PROW) + ks * 32);
                #pragma unroll
                for (int hf = 0; hf < 2; ++hf) {
                    const int nt = np * 2 + hf;
                    mma_bf16(D[nt],  A0, B0[2 * hf], B0[2 * hf + 1]);
                    mma_bf16(Dc[nt], A0, B1[2 * hf], B1[2 * hf + 1]);
                    mma_bf16(Dc[nt], A1, B0[2 * hf], B0[2 * hf + 1]);
                }
            }
        }

        // ---- write U: lane-contiguous 8-loop-warp layout, 4x STG.128 ----
        const size_t biBlk = ((size_t)blk * 32 >> 4) + rg;
        #pragma unroll
        for (int lwh = 0; lwh < 2; ++lwh) {
            const int lw = 2 * (warp & 3) + lwh;
            #pragma unroll
            for (int r = 0; r < 2; ++r) {
                uint4 o;
                #pragma unroll
                for (int ntl = 0; ntl < 2; ++ntl) {
                    const int nt = lwh * 2 + ntl;
                    float s0 = D[nt][2 * r]     + Dc[nt][2 * r];
                    float s1 = D[nt][2 * r + 1] + Dc[nt][2 * r + 1];
                    uint32_t p, pr;
                    split_pair(s0, s1, p, pr);
                    if (ntl == 0) {
                        o.x = __byte_perm(p, pr, 0x5410);
                        o.y = __byte_perm(p, pr, 0x7632);
                    } else {
                        o.z = __byte_perm(p, pr, 0x5410);
                        o.w = __byte_perm(p, pr, 0x7632);
                    }
                }
                *(uint4*)&g_U[biBlk * 2048 + lw * 256 + lane * 8 + r * 4] = o;
            }
        }

        blk = nblk;
        cur ^= 1;
    }
}

// ============ Kernel 2: recurrence, 12 mma chains, hoisted U unpack ========

#define ROWB 272
#define WSPL (HID * ROWB)
#define ASPL (16 * ROWB)
#define ABUF (2 * ASPL)
#define SM_W 0
#define SM_A (2 * WSPL)
#define L_SMEM (SM_A + 2 * ABUF)
#define L_THREADS 256

__global__ void __launch_bounds__(L_THREADS, 1)
loop_kernel(const float* __restrict__ h0, const float* __restrict__ bhh,
            const float* __restrict__ Whh, float* __restrict__ out)
{
    extern __shared__ unsigned char smem[];
    const uint32_t smem_b = smem_u32(smem);

    const int tid  = threadIdx.x;
    const int warp = tid >> 5;
    const int lane = tid & 31;
    const int g    = lane >> 2;
    const int tq   = lane & 3;
    const int bx   = blockIdx.x;
    const int rowBase = bx * 16;
    const int colW = warp * 16;

    for (int idx = tid; idx < HID * HID; idx += L_THREADS) {
        const int n = idx >> 7, k = idx & 127;
        float w = Whh[idx];
        __nv_bfloat16 w0 = __float2bfloat16(w);
        __nv_bfloat16 w1 = __float2bfloat16(w - __bfloat162float(w0));
        const size_t off = (size_t)n * ROWB + (size_t)k * 2;
        *(__nv_bfloat16*)(smem + SM_W + off)        = w0;
        *(__nv_bfloat16*)(smem + SM_W + WSPL + off) = w1;
    }

    float bh0[2], bh1[2];
    #pragma unroll
    for (int nt = 0; nt < 2; ++nt) {
        bh0[nt] = bhh[colW + nt * 8 + tq * 2];
        bh1[nt] = bhh[colW + nt * 8 + tq * 2 + 1];
    }

    // lane-contiguous U address (8 u32 per lane per bi)
    #define UADDR(bi) ((size_t)(bi) * 2048 + warp * 256 + lane * 8)

    // ---- h, a registers; stage a(0) splits ----
    float h[2][2][2], a[2][2][2];
    {
        uint4 u0 = *(const uint4*)&g_U[UADDR(bx)];      // r=0
        uint4 u1 = *(const uint4*)&g_U[UADDR(bx) + 4];  // r=1
        #pragma unroll
        for (int r = 0; r < 2; ++r) {
            const int row = rowBase + g + 8 * r;
            const uint4 uu = r ? u1 : u0;
            #pragma unroll
            for (int nt = 0; nt < 2; ++nt) {
                float2 hv = *(const float2*)&h0[(size_t)row * HID + colW + nt * 8 + tq * 2];
                h[r][nt][0] = hv.x; h[r][nt][1] = hv.y;
                const uint32_t ux = nt ? uu.z : uu.x;
                const uint32_t uy = nt ? uu.w : uu.y;
                a[r][nt][0] = su(ux) * hv.x;
                a[r][nt][1] = su(uy) * hv.y;
            }
        }
    }
    #pragma unroll
    for (int r = 0; r < 2; ++r) {
        const int lrow = g + 8 * r;
        #pragma unroll
        for (int nt = 0; nt < 2; ++nt) {
            uint32_t p, pr;
            split_pair_t(a[r][nt][0], a[r][nt][1], p, pr);
            const size_t o = (size_t)lrow * ROWB + (size_t)(colW + nt * 8 + tq * 2) * 2;
            *(uint32_t*)(smem + SM_A + o)        = p;
            *(uint32_t*)(smem + SM_A + ASPL + o) = pr;
        }
    }

    // ---- 2-deep U prefetch: Ua = U(1), Ub = U(2) ----
    uint4 Ua[2], Ub[2];
    Ua[0] = *(const uint4*)&g_U[UADDR(128 + bx)];
    Ua[1] = *(const uint4*)&g_U[UADDR(128 + bx) + 4];
    Ub[0] = *(const uint4*)&g_U[UADDR(256 + bx)];
    Ub[1] = *(const uint4*)&g_U[UADDR(256 + bx) + 4];
    __syncthreads();

    const int q  = lane >> 3;
    const int lr = lane & 7;
    const uint32_t a_off = (uint32_t)((lr + (q & 1) * 8) * ROWB + ((q & 2) ? 8 : 0) * 2);
    const uint32_t b_off = smem_b + SM_W +
        (uint32_t)((colW + lr + ((q & 2) ? 8 : 0)) * ROWB + ((q & 1) ? 8 : 0) * 2);

    // ---- preload W_hh B-fragments (loop-invariant) ----
    uint32_t Bf0[8][4], Bf1[8][4];
    #pragma unroll
    for (int ks = 0; ks < 8; ++ks) {
        ldsm4(Bf0[ks], b_off + ks * 32);
        ldsm4(Bf1[ks], b_off + WSPL + ks * 32);
    }

    const uint32_t abase = smem_b + SM_A;

    for (int t = 0; t < S_LEN; ++t) {
        const int buf = t & 1;

        // ---- hoisted U(t+1) unpack ----
        float Uf[2][2][2];
        #pragma unroll
        for (int r = 0; r < 2; ++r) {
            Uf[r][0][0] = su(Ua[r].x);
            Uf[r][0][1] = su(Ua[r].y);
            Uf[r][1][0] = su(Ua[r].z);
            Uf[r][1][1] = su(Ua[r].w);
        }

        // ---- mma: 3 products x 2 ks-parities = 12 chains of depth 4 ----
        float D0[2][2][4], D1[2][2][4], D2[2][2][4];
        #pragma unroll
        for (int nt = 0; nt < 2; ++nt) {
            D0[0][nt][0] = bh0[nt]; D0[0][nt][1] = bh1[nt];
            D0[0][nt][2] = bh0[nt]; D0[0][nt][3] = bh1[nt];
            #pragma unroll
            for (int e = 0; e < 4; ++e) {
                D0[1][nt][e] = 0.0f;
                D1[0][nt][e] = 0.0f; D1[1][nt][e] = 0.0f;
                D2[0][nt][e] = 0.0f; D2[1][nt][e] = 0.0f;
            }
        }

        const uint32_t abuf = abase + (uint32_t)buf * ABUF + a_off;
        #pragma unroll
        for (int ks = 0; ks < 8; ++ks) {
            const int par = ks & 1;
            uint32_t A0[4], A1[4];
            ldsm4(A0, abuf + ks * 32);
            ldsm4(A1, abuf + ASPL + ks * 32);
            #pragma unroll
            for (int nt = 0; nt < 2; ++nt) {
                mma_bf16(D0[par][nt], A0, Bf0[ks][2 * nt], Bf0[ks][2 * nt + 1]);
                mma_bf16(D1[par][nt], A0, Bf1[ks][2 * nt], Bf1[ks][2 * nt + 1]);
                mma_bf16(D2[par][nt], A1, Bf0[ks][2 * nt], Bf0[ks][2 * nt + 1]);
            }
        }

        // ---- epilogue ----
        #pragma unroll
        for (int r = 0; r < 2; ++r) {
            const int lrow = g + 8 * r;
            #pragma unroll
            for (int nt = 0; nt < 2; ++nt) {
                float P0 = (D0[0][nt][2 * r]     + D0[1][nt][2 * r]) +
                           (D1[0][nt][2 * r]     + D1[1][nt][2 * r]) +
                           (D2[0][nt][2 * r]     + D2[1][nt][2 * r]);
                float P1 = (D0[0][nt][2 * r + 1] + D0[1][nt][2 * r + 1]) +
                           (D1[0][nt][2 * r + 1] + D1[1][nt][2 * r + 1]) +
                           (D2[0][nt][2 * r + 1] + D2[1][nt][2 * r + 1]);
                float h0n = fast_tanh(fmaf(P0, h[r][nt][0], a[r][nt][0]));
                float h1n = fast_tanh(fmaf(P1, h[r][nt][1], a[r][nt][1]));
                h[r][nt][0] = h0n; h[r][nt][1] = h1n;
                float v0 = Uf[r][nt][0] * h0n;
                float v1 = Uf[r][nt][1] * h1n;
                a[r][nt][0] = v0; a[r][nt][1] = v1;

                uint32_t p, pr;
                split_pair_t(v0, v1, p, pr);
                const size_t o = (size_t)(buf ^ 1) * ABUF + (size_t)lrow * ROWB +
                                 (size_t)(colW + nt * 8 + tq * 2) * 2;
                *(uint32_t*)(smem + SM_A + o)        = p;
                *(uint32_t*)(smem + SM_A + ASPL + o) = pr;
            }
        }

        // ---- shift prefetch: Ua <- Ub, issue Ub = U(t+3) ----
        {
            const int tn = (t + 3 < S_LEN) ? t + 3 : S_LEN - 1;
            const size_t ub = UADDR(tn * 128 + bx);
            Ua[0] = Ub[0]; Ua[1] = Ub[1];
            Ub[0] = *(const uint4*)&g_U[ub];
            Ub[1] = *(const uint4*)&g_U[ub + 4];
        }
        __syncthreads();
    }

    #pragma unroll
    for (int r = 0; r < 2; ++r) {
        const int row = rowBase + g + 8 * r;
        #pragma unroll
        for (int nt = 0; nt < 2; ++nt)
            *(float2*)&out[(size_t)row * HID + colW + nt * 8 + tq * 2] =
                make_float2(h[r][nt][0], h[r][nt][1]);
    }
}

// ============================== launch =====================================

extern "C" void kernel_launch(void* const* d_in, const int* in_sizes, int n_in,
                              void* d_out, int out_size)
{
    const float* x   = (const float*)d_in[0];
    const float* h0  = (const float*)d_in[1];
    const float* Wih = (const float*)d_in[2];
    const float* bih = (const float*)d_in[3];
    const float* Whh = (const float*)d_in[4];
    const float* bhh = (const float*)d_in[5];

    cudaFuncSetAttribute(precompute_kernel,
                         cudaFuncAttributeMaxDynamicSharedMemorySize, P2_SMEM);
    precompute_kernel<<<P2_GRID, P2_THREADS, P2_SMEM>>>(x, Wih, bih);

    cudaFuncSetAttribute(loop_kernel,
                         cudaFuncAttributeMaxDynamicSharedMemorySize, L_SMEM);
    loop_kernel<<<BATCH / 16, L_THREADS, L_SMEM>>>(h0, bhh, Whh, (float*)d_out);
}

// round 15
// speedup vs baseline: 1.1473x; 1.1238x over previous
#include <cuda_runtime.h>
#include <cuda_bf16.h>
#include <cstdint>

#define S_LEN 512
#define BATCH 2048
#define DIN 64
#define HID 128
#define NROWS (S_LEN * BATCH)

// U scratch (split-packed bf16 pairs), dense-dual layout:
// u32 index = bi*2048 + r*1024 + cw*128 + lane*4 + nt*2 + e
__device__ uint32_t g_U[(size_t)NROWS * HID];

__device__ __forceinline__ float fast_tanh(float v) {
    float r;
    asm("tanh.approx.f32 %0, %1;" : "=f"(r) : "f"(v));
    return r;
}
__device__ __forceinline__ void ldsm4(uint32_t r[4], uint32_t addr) {
    asm volatile("ldmatrix.sync.aligned.m8n8.x4.shared.b16 {%0,%1,%2,%3}, [%4];"
                 : "=r"(r[0]), "=r"(r[1]), "=r"(r[2]), "=r"(r[3]) : "r"(addr));
}
__device__ __forceinline__ void mma_bf16(float d[4], const uint32_t a[4],
                                         const uint32_t b0, const uint32_t b1) {
    asm volatile("mma.sync.aligned.m16n8k16.row.col.f32.bf16.bf16.f32 "
                 "{%0,%1,%2,%3}, {%4,%5,%6,%7}, {%8,%9}, {%0,%1,%2,%3};"
                 : "+f"(d[0]), "+f"(d[1]), "+f"(d[2]), "+f"(d[3])
                 : "r"(a[0]), "r"(a[1]), "r"(a[2]), "r"(a[3]), "r"(b0), "r"(b1));
}
__device__ __forceinline__ uint32_t smem_u32(const void* p) {
    uint32_t a;
    asm("{ .reg .u64 t; cvta.to.shared.u64 t, %1; cvt.u32.u64 %0, t; }"
        : "=r"(a) : "l"(p));
    return a;
}
__device__ __forceinline__ uint32_t cvt2bf(float lo, float hi) {
    uint32_t r;
    asm("cvt.rn.bf16x2.f32 %0, %1, %2;" : "=r"(r) : "f"(hi), "f"(lo));
    return r;
}
// packed split element: low16 = main bf16, high16 = residual bf16
__device__ __forceinline__ float su(uint32_t p) {
    return __uint_as_float(p << 16) + __uint_as_float(p & 0xFFFF0000u);
}
// round-to-nearest split (precompute path)
__device__ __forceinline__ void split_pair(float v0, float v1,
                                           uint32_t& hi, uint32_t& lo) {
    hi = cvt2bf(v0, v1);
    float f0 = __uint_as_float(hi << 16);
    float f1 = __uint_as_float(hi & 0xFFFF0000u);
    lo = cvt2bf(v0 - f0, v1 - f1);
}
// truncation split: main plane via PRMT, residual exact
__device__ __forceinline__ void split_pair_t(float v0, float v1,
                                             uint32_t& hi, uint32_t& lo) {
    const uint32_t b0 = __float_as_uint(v0), b1 = __float_as_uint(v1);
    hi = __byte_perm(b0, b1, 0x7632);
    float r0 = v0 - __uint_as_float(b0 & 0xFFFF0000u);
    float r1 = v1 - __uint_as_float(b1 & 0xFFFF0000u);
    lo = cvt2bf(r0, r1);
}

// ============ Kernel 1: U = x @ W_ih^T + b_ih via bf16 mma ================

#define P2_THREADS 256
#define P2_GRID 592
#define NTILES (NROWS / 32)
#define PROW 144
#define PWSPL (HID * PROW)
#define PXSPL (32 * PROW)
#define PXBUF (2 * PXSPL)
#define PW 0
#define PX (2 * PWSPL)
#define P2_SMEM (PX + 2 * PXBUF)

__global__ void __launch_bounds__(P2_THREADS)
precompute_kernel(const float* __restrict__ x, const float* __restrict__ Wih,
                  const float* __restrict__ bih)
{
    extern __shared__ unsigned char sm[];
    const uint32_t smem_b = smem_u32(sm);

    const int tid  = threadIdx.x;
    const int warp = tid >> 5;
    const int lane = tid & 31;
    const int tq   = lane & 3;
    const int rg   = warp >> 2;
    const int pwc  = warp & 3;
    const int colWp = pwc * 32;

    // ---- stage W_ih splits (once) ----
    for (int idx = tid; idx < HID * DIN; idx += P2_THREADS) {
        const int n = idx >> 6, k = idx & 63;
        float w = Wih[idx];
        __nv_bfloat16 w0 = __float2bfloat16(w);
        __nv_bfloat16 w1 = __float2bfloat16(w - __bfloat162float(w0));
        const size_t off = (size_t)n * PROW + (size_t)k * 2;
        *(__nv_bfloat16*)(sm + PW + off)         = w0;
        *(__nv_bfloat16*)(sm + PW + PWSPL + off) = w1;
    }

    float bi0[4], bi1[4];
    #pragma unroll
    for (int nt = 0; nt < 4; ++nt) {
        bi0[nt] = bih[colWp + nt * 8 + tq * 2];
        bi1[nt] = bih[colWp + nt * 8 + tq * 2 + 1];
    }

    const int q  = lane >> 3;
    const int lr = lane & 7;
    const uint32_t xa_lane = (uint32_t)((rg * 16 + lr + (q & 1) * 8) * PROW +
                                        ((q & 2) ? 8 : 0) * 2);
    const uint32_t wb = smem_b + PW +
        (uint32_t)((colWp + lr + ((q & 2) ? 8 : 0)) * PROW + ((q & 1) ? 8 : 0) * 2);

    const int sr = tid >> 3;
    const int sc = (tid & 7) * 8;

    // ---- prologue: load x for first tile (single-deep prefetch) ----
    int blk = blockIdx.x;
    float4 v0, v1;
    if (blk < NTILES) {
        const float* p = x + ((size_t)blk * 32 + sr) * DIN + sc;
        v0 = *(const float4*)p; v1 = *(const float4*)(p + 4);
    }
    int cur = 0;
    __syncthreads();

    while (blk < NTILES) {
        // ---- stage x tile splits: 2x STS.128 per thread ----
        {
            uint4 hi, lo;
            split_pair(v0.x, v0.y, hi.x, lo.x);
            split_pair(v0.z, v0.w, hi.y, lo.y);
            split_pair(v1.x, v1.y, hi.z, lo.z);
            split_pair(v1.z, v1.w, hi.w, lo.w);
            unsigned char* xb = sm + PX + cur * PXBUF + sr * PROW + sc * 2;
            *(uint4*)xb           = hi;
            *(uint4*)(xb + PXSPL) = lo;
        }
        __syncthreads();

        // ---- prefetch next tile ----
        const int nblk = blk + P2_GRID;
        if (nblk < NTILES) {
            const float* p = x + ((size_t)nblk * 32 + sr) * DIN + sc;
            v0 = *(const float4*)p; v1 = *(const float4*)(p + 4);
        }

        // ---- mma: 2-way splits, 3 products ----
        float D[4][4], Dc[4][4];
        #pragma unroll
        for (int nt = 0; nt < 4; ++nt) {
            D[nt][0] = bi0[nt]; D[nt][1] = bi1[nt];
            D[nt][2] = bi0[nt]; D[nt][3] = bi1[nt];
            Dc[nt][0] = Dc[nt][1] = Dc[nt][2] = Dc[nt][3] = 0.0f;
        }
        const uint32_t xa = smem_b + PX + (uint32_t)cur * PXBUF + xa_lane;
        #pragma unroll
        for (int ks = 0; ks < 4; ++ks) {
            uint32_t A0[4], A1[4];
            ldsm4(A0, xa + ks * 32);
            ldsm4(A1, xa + PXSPL + ks * 32);
            #pragma unroll
            for (int np = 0; np < 2; ++np) {
                uint32_t B0[4], B1[4];
                ldsm4(B0, wb + (uint32_t)(np * 16 * PROW) + ks * 32);
                ldsm4(B1, wb + PWSPL + (uint32_t)(np * 16 * PROW) + ks * 32);
                #pragma unroll
                for (int hf = 0; hf < 2; ++hf) {
                    const int nt = np * 2 + hf;
                    mma_bf16(D[nt],  A0, B0[2 * hf], B0[2 * hf + 1]);
                    mma_bf16(Dc[nt], A0, B1[2 * hf], B1[2 * hf + 1]);
                    mma_bf16(Dc[nt], A1, B0[2 * hf], B0[2 * hf + 1]);
                }
            }
        }

        // ---- write U: 4x fully-dense STG.128 per lane ----
        const size_t biBlk = ((size_t)blk * 32 >> 4) + rg;
        #pragma unroll
        for (int lwh = 0; lwh < 2; ++lwh) {
            const int cw = pwc * 2 + lwh;
            #pragma unroll
            for (int r = 0; r < 2; ++r) {
                uint4 o;
                #pragma unroll
                for (int ntl = 0; ntl < 2; ++ntl) {
                    const int nt = lwh * 2 + ntl;
                    float s0 = D[nt][2 * r]     + Dc[nt][2 * r];
                    float s1 = D[nt][2 * r + 1] + Dc[nt][2 * r + 1];
                    uint32_t p, pr;
                    split_pair(s0, s1, p, pr);
                    if (ntl == 0) {
                        o.x = __byte_perm(p, pr, 0x5410);
                        o.y = __byte_perm(p, pr, 0x7632);
                    } else {
                        o.z = __byte_perm(p, pr, 0x5410);
                        o.w = __byte_perm(p, pr, 0x7632);
                    }
                }
                *(uint4*)&g_U[biBlk * 2048 + (size_t)r * 1024 +
                              (size_t)cw * 128 + lane * 4] = o;
            }
        }

        blk = nblk;
        cur ^= 1;
    }
}

// ============ Kernel 2: recurrence, 12 mma chains, hoisted U unpack ========

#define ROWB 272
#define WSPL (HID * ROWB)
#define ASPL (16 * ROWB)
#define ABUF (2 * ASPL)
#define SM_W 0
#define SM_A (2 * WSPL)
#define L_SMEM (SM_A + 2 * ABUF)
#define L_THREADS 256

__global__ void __launch_bounds__(L_THREADS, 1)
loop_kernel(const float* __restrict__ h0, const float* __restrict__ bhh,
            const float* __restrict__ Whh, float* __restrict__ out)
{
    extern __shared__ unsigned char smem[];
    const uint32_t smem_b = smem_u32(smem);

    const int tid  = threadIdx.x;
    const int warp = tid >> 5;
    const int lane = tid & 31;
    const int g    = lane >> 2;
    const int tq   = lane & 3;
    const int bx   = blockIdx.x;
    const int rowBase = bx * 16;
    const int colW = warp * 16;

    for (int idx = tid; idx < HID * HID; idx += L_THREADS) {
        const int n = idx >> 7, k = idx & 127;
        float w = Whh[idx];
        __nv_bfloat16 w0 = __float2bfloat16(w);
        __nv_bfloat16 w1 = __float2bfloat16(w - __bfloat162float(w0));
        const size_t off = (size_t)n * ROWB + (size_t)k * 2;
        *(__nv_bfloat16*)(smem + SM_W + off)        = w0;
        *(__nv_bfloat16*)(smem + SM_W + WSPL + off) = w1;
    }

    float bh0[2], bh1[2];
    #pragma unroll
    for (int nt = 0; nt < 2; ++nt) {
        bh0[nt] = bhh[colW + nt * 8 + tq * 2];
        bh1[nt] = bhh[colW + nt * 8 + tq * 2 + 1];
    }

    // dense-dual U address: uint4 per (bi, r)
    #define UADDR(bi, r) ((size_t)(bi) * 2048 + (size_t)(r) * 1024 + \
                          (size_t)warp * 128 + lane * 4)

    // ---- h, a registers; stage a(0) splits ----
    float h[2][2][2], a[2][2][2];
    {
        uint4 u0 = *(const uint4*)&g_U[UADDR(bx, 0)];
        uint4 u1 = *(const uint4*)&g_U[UADDR(bx, 1)];
        #pragma unroll
        for (int r = 0; r < 2; ++r) {
            const int row = rowBase + g + 8 * r;
            const uint4 uu = r ? u1 : u0;
            #pragma unroll
            for (int nt = 0; nt < 2; ++nt) {
                float2 hv = *(const float2*)&h0[(size_t)row * HID + colW + nt * 8 + tq * 2];
                h[r][nt][0] = hv.x; h[r][nt][1] = hv.y;
                const uint32_t ux = nt ? uu.z : uu.x;
                const uint32_t uy = nt ? uu.w : uu.y;
                a[r][nt][0] = su(ux) * hv.x;
                a[r][nt][1] = su(uy) * hv.y;
            }
        }
    }
    #pragma unroll
    for (int r = 0; r < 2; ++r) {
        const int lrow = g + 8 * r;
        #pragma unroll
        for (int nt = 0; nt < 2; ++nt) {
            uint32_t p, pr;
            split_pair_t(a[r][nt][0], a[r][nt][1], p, pr);
            const size_t o = (size_t)lrow * ROWB + (size_t)(colW + nt * 8 + tq * 2) * 2;
            *(uint32_t*)(smem + SM_A + o)        = p;
            *(uint32_t*)(smem + SM_A + ASPL + o) = pr;
        }
    }

    // ---- 2-deep U prefetch: Ua = U(1), Ub = U(2) ----
    uint4 Ua[2], Ub[2];
    Ua[0] = *(const uint4*)&g_U[UADDR(128 + bx, 0)];
    Ua[1] = *(const uint4*)&g_U[UADDR(128 + bx, 1)];
    Ub[0] = *(const uint4*)&g_U[UADDR(256 + bx, 0)];
    Ub[1] = *(const uint4*)&g_U[UADDR(256 + bx, 1)];
    __syncthreads();

    const int q  = lane >> 3;
    const int lr = lane & 7;
    const uint32_t a_off = (uint32_t)((lr + (q & 1) * 8) * ROWB + ((q & 2) ? 8 : 0) * 2);
    const uint32_t b_off = smem_b + SM_W +
        (uint32_t)((colW + lr + ((q & 2) ? 8 : 0)) * ROWB + ((q & 1) ? 8 : 0) * 2);

    // ---- preload W_hh B-fragments (loop-invariant) ----
    uint32_t Bf0[8][4], Bf1[8][4];
    #pragma unroll
    for (int ks = 0; ks < 8; ++ks) {
        ldsm4(Bf0[ks], b_off + ks * 32);
        ldsm4(Bf1[ks], b_off + WSPL + ks * 32);
    }

    const uint32_t abase = smem_b + SM_A;

    for (int t = 0; t < S_LEN; ++t) {
        const int buf = t & 1;

        // ---- hoisted U(t+1) unpack ----
        float Uf[2][2][2];
        #pragma unroll
        for (int r = 0; r < 2; ++r) {
            Uf[r][0][0] = su(Ua[r].x);
            Uf[r][0][1] = su(Ua[r].y);
            Uf[r][1][0] = su(Ua[r].z);
            Uf[r][1][1] = su(Ua[r].w);
        }

        // ---- mma: 3 products x 2 ks-parities = 12 chains of depth 4 ----
        float D0[2][2][4], D1[2][2][4], D2[2][2][4];
        #pragma unroll
        for (int nt = 0; nt < 2; ++nt) {
            D0[0][nt][0] = bh0[nt]; D0[0][nt][1] = bh1[nt];
            D0[0][nt][2] = bh0[nt]; D0[0][nt][3] = bh1[nt];
            #pragma unroll
            for (int e = 0; e < 4; ++e) {
                D0[1][nt][e] = 0.0f;
                D1[0][nt][e] = 0.0f; D1[1][nt][e] = 0.0f;
                D2[0][nt][e] = 0.0f; D2[1][nt][e] = 0.0f;
            }
        }

        const uint32_t abuf = abase + (uint32_t)buf * ABUF + a_off;
        #pragma unroll
        for (int ks = 0; ks < 8; ++ks) {
            const int par = ks & 1;
            uint32_t A0[4], A1[4];
            ldsm4(A0, abuf + ks * 32);
            ldsm4(A1, abuf + ASPL + ks * 32);
            #pragma unroll
            for (int nt = 0; nt < 2; ++nt) {
                mma_bf16(D0[par][nt], A0, Bf0[ks][2 * nt], Bf0[ks][2 * nt + 1]);
                mma_bf16(D1[par][nt], A0, Bf1[ks][2 * nt], Bf1[ks][2 * nt + 1]);
                mma_bf16(D2[par][nt], A1, Bf0[ks][2 * nt], Bf0[ks][2 * nt + 1]);
            }
        }

        // ---- epilogue ----
        #pragma unroll
        for (int r = 0; r < 2; ++r) {
            const int lrow = g + 8 * r;
            #pragma unroll
            for (int nt = 0; nt < 2; ++nt) {
                float P0 = (D0[0][nt][2 * r]     + D0[1][nt][2 * r]) +
                           (D1[0][nt][2 * r]     + D1[1][nt][2 * r]) +
                           (D2[0][nt][2 * r]     + D2[1][nt][2 * r]);
                float P1 = (D0[0][nt][2 * r + 1] + D0[1][nt][2 * r + 1]) +
                           (D1[0][nt][2 * r + 1] + D1[1][nt][2 * r + 1]) +
                           (D2[0][nt][2 * r + 1] + D2[1][nt][2 * r + 1]);
                float h0n = fast_tanh(fmaf(P0, h[r][nt][0], a[r][nt][0]));
                float h1n = fast_tanh(fmaf(P1, h[r][nt][1], a[r][nt][1]));
                h[r][nt][0] = h0n; h[r][nt][1] = h1n;
                float v0 = Uf[r][nt][0] * h0n;
                float v1 = Uf[r][nt][1] * h1n;
                a[r][nt][0] = v0; a[r][nt][1] = v1;

                uint32_t p, pr;
                split_pair_t(v0, v1, p, pr);
                const size_t o = (size_t)(buf ^ 1) * ABUF + (size_t)lrow * ROWB +
                                 (size_t)(colW + nt * 8 + tq * 2) * 2;
                *(uint32_t*)(smem + SM_A + o)        = p;
                *(uint32_t*)(smem + SM_A + ASPL + o) = pr;
            }
        }

        // ---- shift prefetch: Ua <- Ub, issue Ub = U(t+3) ----
        {
            const int tn = (t + 3 < S_LEN) ? t + 3 : S_LEN - 1;
            Ua[0] = Ub[0]; Ua[1] = Ub[1];
            Ub[0] = *(const uint4*)&g_U[UADDR(tn * 128 + bx, 0)];
            Ub[1] = *(const uint4*)&g_U[UADDR(tn * 128 + bx, 1)];
        }
        __syncthreads();
    }

    #pragma unroll
    for (int r = 0; r < 2; ++r) {
        const int row = rowBase + g + 8 * r;
        #pragma unroll
        for (int nt = 0; nt < 2; ++nt)
            *(float2*)&out[(size_t)row * HID + colW + nt * 8 + tq * 2] =
                make_float2(h[r][nt][0], h[r][nt][1]);
    }
}

// ============================== launch =====================================

extern "C" void kernel_launch(void* const* d_in, const int* in_sizes, int n_in,
                              void* d_out, int out_size)
{
    const float* x   = (const float*)d_in[0];
    const float* h0  = (const float*)d_in[1];
    const float* Wih = (const float*)d_in[2];
    const float* bih = (const float*)d_in[3];
    const float* Whh = (const float*)d_in[4];
    const float* bhh = (const float*)d_in[5];

    cudaFuncSetAttribute(precompute_kernel,
                         cudaFuncAttributeMaxDynamicSharedMemorySize, P2_SMEM);
    precompute_kernel<<<P2_GRID, P2_THREADS, P2_SMEM>>>(x, Wih, bih);

    cudaFuncSetAttribute(loop_kernel,
                         cudaFuncAttributeMaxDynamicSharedMemorySize, L_SMEM);
    loop_kernel<<<BATCH / 16, L_THREADS, L_SMEM>>>(h0, bhh, Whh, (float*)d_out);
}

// round 16
// speedup vs baseline: 1.2771x; 1.1131x over previous
#include <cuda_runtime.h>
#include <cuda_bf16.h>
#include <cuda_fp16.h>
#include <cstdint>

#define S_LEN 512
#define BATCH 2048
#define DIN 64
#define HID 128
#define NROWS (S_LEN * BATCH)

// U scratch (split-packed bf16 pairs), dense-dual layout:
// u32 index = bi*2048 + r*1024 + cw*128 + lane*4 + nt*2 + e
__device__ uint32_t g_U[(size_t)NROWS * HID];

__device__ __forceinline__ float fast_tanh(float v) {
    float r;
    asm("tanh.approx.f32 %0, %1;" : "=f"(r) : "f"(v));
    return r;
}
__device__ __forceinline__ void ldsm4(uint32_t r[4], uint32_t addr) {
    asm volatile("ldmatrix.sync.aligned.m8n8.x4.shared.b16 {%0,%1,%2,%3}, [%4];"
                 : "=r"(r[0]), "=r"(r[1]), "=r"(r[2]), "=r"(r[3]) : "r"(addr));
}
__device__ __forceinline__ void mma_f16(float d[4], const uint32_t a[4],
                                        const uint32_t b0, const uint32_t b1) {
    asm volatile("mma.sync.aligned.m16n8k16.row.col.f32.f16.f16.f32 "
                 "{%0,%1,%2,%3}, {%4,%5,%6,%7}, {%8,%9}, {%0,%1,%2,%3};"
                 : "+f"(d[0]), "+f"(d[1]), "+f"(d[2]), "+f"(d[3])
                 : "r"(a[0]), "r"(a[1]), "r"(a[2]), "r"(a[3]), "r"(b0), "r"(b1));
}
__device__ __forceinline__ uint32_t smem_u32(const void* p) {
    uint32_t a;
    asm("{ .reg .u64 t; cvta.to.shared.u64 t, %1; cvt.u32.u64 %0, t; }"
        : "=r"(a) : "l"(p));
    return a;
}
__device__ __forceinline__ uint32_t cvt2bf(float lo, float hi) {
    uint32_t r;
    asm("cvt.rn.bf16x2.f32 %0, %1, %2;" : "=r"(r) : "f"(hi), "f"(lo));
    return r;
}
__device__ __forceinline__ uint32_t cvt2h(float lo, float hi) {
    uint32_t r;
    asm("cvt.rn.f16x2.f32 %0, %1, %2;" : "=r"(r) : "f"(hi), "f"(lo));
    return r;
}
// packed split element: low16 = main bf16, high16 = residual bf16
__device__ __forceinline__ float su(uint32_t p) {
    return __uint_as_float(p << 16) + __uint_as_float(p & 0xFFFF0000u);
}
// round-to-nearest bf16 split (U packing)
__device__ __forceinline__ void split_pair(float v0, float v1,
                                           uint32_t& hi, uint32_t& lo) {
    hi = cvt2bf(v0, v1);
    float f0 = __uint_as_float(hi << 16);
    float f1 = __uint_as_float(hi & 0xFFFF0000u);
    lo = cvt2bf(v0 - f0, v1 - f1);
}

// ============ Kernel 1: U = x @ W_ih^T + b_ih via fp16 mma ================
// x single fp16 plane; W_ih two fp16 planes; 2 products.

#define P2_THREADS 256
#define P2_GRID 592
#define NTILES (NROWS / 32)
#define PROW 144
#define PWSPL (HID * PROW)          // 18432 per W_ih plane
#define PXSPL (32 * PROW)           // 4608 single x plane
#define PW 0
#define PX (2 * PWSPL)              // 36864
#define P2_SMEM (PX + 2 * PXSPL)    // 46080

__global__ void __launch_bounds__(P2_THREADS)
precompute_kernel(const float* __restrict__ x, const float* __restrict__ Wih,
                  const float* __restrict__ bih)
{
    extern __shared__ unsigned char sm[];
    const uint32_t smem_b = smem_u32(sm);

    const int tid  = threadIdx.x;
    const int warp = tid >> 5;
    const int lane = tid & 31;
    const int tq   = lane & 3;
    const int rg   = warp >> 2;
    const int pwc  = warp & 3;
    const int colWp = pwc * 32;

    // ---- stage W_ih fp16 planes (once) ----
    for (int idx = tid; idx < HID * DIN; idx += P2_THREADS) {
        const int n = idx >> 6, k = idx & 63;
        float w = Wih[idx];
        __half w0 = __float2half_rn(w);
        __half w1 = __float2half_rn(w - __half2float(w0));
        const size_t off = (size_t)n * PROW + (size_t)k * 2;
        *(__half*)(sm + PW + off)         = w0;
        *(__half*)(sm + PW + PWSPL + off) = w1;
    }

    float bi0[4], bi1[4];
    #pragma unroll
    for (int nt = 0; nt < 4; ++nt) {
        bi0[nt] = bih[colWp + nt * 8 + tq * 2];
        bi1[nt] = bih[colWp + nt * 8 + tq * 2 + 1];
    }

    const int q  = lane >> 3;
    const int lr = lane & 7;
    const uint32_t xa_lane = (uint32_t)((rg * 16 + lr + (q & 1) * 8) * PROW +
                                        ((q & 2) ? 8 : 0) * 2);
    const uint32_t wb = smem_b + PW +
        (uint32_t)((colWp + lr + ((q & 2) ? 8 : 0)) * PROW + ((q & 1) ? 8 : 0) * 2);

    const int sr = tid >> 3;
    const int sc = (tid & 7) * 8;

    // ---- prologue: load x for first tile ----
    int blk = blockIdx.x;
    float4 v0, v1;
    if (blk < NTILES) {
        const float* p = x + ((size_t)blk * 32 + sr) * DIN + sc;
        v0 = *(const float4*)p; v1 = *(const float4*)(p + 4);
    }
    int cur = 0;
    __syncthreads();

    while (blk < NTILES) {
        // ---- stage x tile (single fp16 plane): 1x STS.128 per thread ----
        {
            uint4 o;
            o.x = cvt2h(v0.x, v0.y);
            o.y = cvt2h(v0.z, v0.w);
            o.z = cvt2h(v1.x, v1.y);
            o.w = cvt2h(v1.z, v1.w);
            *(uint4*)(sm + PX + cur * PXSPL + sr * PROW + sc * 2) = o;
        }
        __syncthreads();

        // ---- prefetch next tile ----
        const int nblk = blk + P2_GRID;
        if (nblk < NTILES) {
            const float* p = x + ((size_t)nblk * 32 + sr) * DIN + sc;
            v0 = *(const float4*)p; v1 = *(const float4*)(p + 4);
        }

        // ---- mma: 2 products (x0*W0, x0*W1) ----
        float D[4][4], Dc[4][4];
        #pragma unroll
        for (int nt = 0; nt < 4; ++nt) {
            D[nt][0] = bi0[nt]; D[nt][1] = bi1[nt];
            D[nt][2] = bi0[nt]; D[nt][3] = bi1[nt];
            Dc[nt][0] = Dc[nt][1] = Dc[nt][2] = Dc[nt][3] = 0.0f;
        }
        const uint32_t xa = smem_b + PX + (uint32_t)cur * PXSPL + xa_lane;
        #pragma unroll
        for (int ks = 0; ks < 4; ++ks) {
            uint32_t A0[4];
            ldsm4(A0, xa + ks * 32);
            #pragma unroll
            for (int np = 0; np < 2; ++np) {
                uint32_t B0[4], B1[4];
                ldsm4(B0, wb + (uint32_t)(np * 16 * PROW) + ks * 32);
                ldsm4(B1, wb + PWSPL + (uint32_t)(np * 16 * PROW) + ks * 32);
                #pragma unroll
                for (int hf = 0; hf < 2; ++hf) {
                    const int nt = np * 2 + hf;
                    mma_f16(D[nt],  A0, B0[2 * hf], B0[2 * hf + 1]);
                    mma_f16(Dc[nt], A0, B1[2 * hf], B1[2 * hf + 1]);
                }
            }
        }

        // ---- write U: 4x fully-dense STG.128 per lane ----
        const size_t biBlk = ((size_t)blk * 32 >> 4) + rg;
        #pragma unroll
        for (int lwh = 0; lwh < 2; ++lwh) {
            const int cw = pwc * 2 + lwh;
            #pragma unroll
            for (int r = 0; r < 2; ++r) {
                uint4 o;
                #pragma unroll
                for (int ntl = 0; ntl < 2; ++ntl) {
                    const int nt = lwh * 2 + ntl;
                    float s0 = D[nt][2 * r]     + Dc[nt][2 * r];
                    float s1 = D[nt][2 * r + 1] + Dc[nt][2 * r + 1];
                    uint32_t p, pr;
                    split_pair(s0, s1, p, pr);
                    if (ntl == 0) {
                        o.x = __byte_perm(p, pr, 0x5410);
                        o.y = __byte_perm(p, pr, 0x7632);
                    } else {
                        o.z = __byte_perm(p, pr, 0x5410);
                        o.w = __byte_perm(p, pr, 0x7632);
                    }
                }
                *(uint4*)&g_U[biBlk * 2048 + (size_t)r * 1024 +
                              (size_t)cw * 128 + lane * 4] = o;
            }
        }

        blk = nblk;
        cur ^= 1;
    }
}

// ====== Kernel 2: recurrence, fp16 2-product GEMM2, 8 mma chains ==========

#define ROWB 272
#define WSPL (HID * ROWB)           // 34816 per W_hh fp16 plane
#define ASPL (16 * ROWB)            // 4352 single a plane
#define SM_W 0
#define SM_A (2 * WSPL)             // 69632
#define L_SMEM (SM_A + 2 * ASPL)    // 78336
#define L_THREADS 256

__global__ void __launch_bounds__(L_THREADS, 1)
loop_kernel(const float* __restrict__ h0, const float* __restrict__ bhh,
            const float* __restrict__ Whh, float* __restrict__ out)
{
    extern __shared__ unsigned char smem[];
    const uint32_t smem_b = smem_u32(smem);

    const int tid  = threadIdx.x;
    const int warp = tid >> 5;
    const int lane = tid & 31;
    const int g    = lane >> 2;
    const int tq   = lane & 3;
    const int bx   = blockIdx.x;
    const int rowBase = bx * 16;
    const int colW = warp * 16;

    // ---- stage W_hh fp16 planes ----
    for (int idx = tid; idx < HID * HID; idx += L_THREADS) {
        const int n = idx >> 7, k = idx & 127;
        float w = Whh[idx];
        __half w0 = __float2half_rn(w);
        __half w1 = __float2half_rn(w - __half2float(w0));
        const size_t off = (size_t)n * ROWB + (size_t)k * 2;
        *(__half*)(smem + SM_W + off)        = w0;
        *(__half*)(smem + SM_W + WSPL + off) = w1;
    }

    float bh0[2], bh1[2];
    #pragma unroll
    for (int nt = 0; nt < 2; ++nt) {
        bh0[nt] = bhh[colW + nt * 8 + tq * 2];
        bh1[nt] = bhh[colW + nt * 8 + tq * 2 + 1];
    }

    // dense-dual U address: uint4 per (bi, r)
    #define UADDR(bi, r) ((size_t)(bi) * 2048 + (size_t)(r) * 1024 + \
                          (size_t)warp * 128 + lane * 4)

    // ---- h, a registers; stage a(0) (single fp16 plane) ----
    float h[2][2][2], a[2][2][2];
    {
        uint4 u0 = *(const uint4*)&g_U[UADDR(bx, 0)];
        uint4 u1 = *(const uint4*)&g_U[UADDR(bx, 1)];
        #pragma unroll
        for (int r = 0; r < 2; ++r) {
            const int row = rowBase + g + 8 * r;
            const uint4 uu = r ? u1 : u0;
            #pragma unroll
            for (int nt = 0; nt < 2; ++nt) {
                float2 hv = *(const float2*)&h0[(size_t)row * HID + colW + nt * 8 + tq * 2];
                h[r][nt][0] = hv.x; h[r][nt][1] = hv.y;
                const uint32_t ux = nt ? uu.z : uu.x;
                const uint32_t uy = nt ? uu.w : uu.y;
                a[r][nt][0] = su(ux) * hv.x;
                a[r][nt][1] = su(uy) * hv.y;
            }
        }
    }
    #pragma unroll
    for (int r = 0; r < 2; ++r) {
        const int lrow = g + 8 * r;
        #pragma unroll
        for (int nt = 0; nt < 2; ++nt) {
            const size_t o = (size_t)lrow * ROWB + (size_t)(colW + nt * 8 + tq * 2) * 2;
            *(uint32_t*)(smem + SM_A + o) = cvt2h(a[r][nt][0], a[r][nt][1]);
        }
    }

    // ---- 2-deep U prefetch ----
    uint4 Ua[2], Ub[2];
    Ua[0] = *(const uint4*)&g_U[UADDR(128 + bx, 0)];
    Ua[1] = *(const uint4*)&g_U[UADDR(128 + bx, 1)];
    Ub[0] = *(const uint4*)&g_U[UADDR(256 + bx, 0)];
    Ub[1] = *(const uint4*)&g_U[UADDR(256 + bx, 1)];
    __syncthreads();

    const int q  = lane >> 3;
    const int lr = lane & 7;
    const uint32_t a_off = (uint32_t)((lr + (q & 1) * 8) * ROWB + ((q & 2) ? 8 : 0) * 2);
    const uint32_t b_off = smem_b + SM_W +
        (uint32_t)((colW + lr + ((q & 2) ? 8 : 0)) * ROWB + ((q & 1) ? 8 : 0) * 2);

    // ---- preload W_hh B-fragments, both planes (loop-invariant) ----
    uint32_t Bf0[8][4], Bf1[8][4];
    #pragma unroll
    for (int ks = 0; ks < 8; ++ks) {
        ldsm4(Bf0[ks], b_off + ks * 32);
        ldsm4(Bf1[ks], b_off + WSPL + ks * 32);
    }

    const uint32_t abase = smem_b + SM_A;

    for (int t = 0; t < S_LEN; ++t) {
        const int buf = t & 1;

        // ---- hoisted U(t+1) unpack ----
        float Uf[2][2][2];
        #pragma unroll
        for (int r = 0; r < 2; ++r) {
            Uf[r][0][0] = su(Ua[r].x);
            Uf[r][0][1] = su(Ua[r].y);
            Uf[r][1][0] = su(Ua[r].z);
            Uf[r][1][1] = su(Ua[r].w);
        }

        // ---- mma: 2 products x 2 ks-parities x 2 nt = 8 chains of depth 4
        float D0[2][2][4], D1[2][2][4];
        #pragma unroll
        for (int nt = 0; nt < 2; ++nt) {
            D0[0][nt][0] = bh0[nt]; D0[0][nt][1] = bh1[nt];
            D0[0][nt][2] = bh0[nt]; D0[0][nt][3] = bh1[nt];
            #pragma unroll
            for (int e = 0; e < 4; ++e) {
                D0[1][nt][e] = 0.0f;
                D1[0][nt][e] = 0.0f; D1[1][nt][e] = 0.0f;
            }
        }

        const uint32_t abuf = abase + (uint32_t)buf * ASPL + a_off;
        #pragma unroll
        for (int ks = 0; ks < 8; ++ks) {
            const int par = ks & 1;
            uint32_t A0[4];
            ldsm4(A0, abuf + ks * 32);
            #pragma unroll
            for (int nt = 0; nt < 2; ++nt) {
                mma_f16(D0[par][nt], A0, Bf0[ks][2 * nt], Bf0[ks][2 * nt + 1]);
                mma_f16(D1[par][nt], A0, Bf1[ks][2 * nt], Bf1[ks][2 * nt + 1]);
            }
        }

        // ---- epilogue ----
        #pragma unroll
        for (int r = 0; r < 2; ++r) {
            const int lrow = g + 8 * r;
            #pragma unroll
            for (int nt = 0; nt < 2; ++nt) {
                float P0 = (D0[0][nt][2 * r]     + D0[1][nt][2 * r]) +
                           (D1[0][nt][2 * r]     + D1[1][nt][2 * r]);
                float P1 = (D0[0][nt][2 * r + 1] + D0[1][nt][2 * r + 1]) +
                           (D1[0][nt][2 * r + 1] + D1[1][nt][2 * r + 1]);
                float h0n = fast_tanh(fmaf(P0, h[r][nt][0], a[r][nt][0]));
                float h1n = fast_tanh(fmaf(P1, h[r][nt][1], a[r][nt][1]));
                h[r][nt][0] = h0n; h[r][nt][1] = h1n;
                float v0 = Uf[r][nt][0] * h0n;
                float v1 = Uf[r][nt][1] * h1n;
                a[r][nt][0] = v0; a[r][nt][1] = v1;

                const size_t o = (size_t)(buf ^ 1) * ASPL + (size_t)lrow * ROWB +
                                 (size_t)(colW + nt * 8 + tq * 2) * 2;
                *(uint32_t*)(smem + SM_A + o) = cvt2h(v0, v1);
            }
        }

        // ---- shift prefetch: Ua <- Ub, issue Ub = U(t+3) ----
        {
            const int tn = (t + 3 < S_LEN) ? t + 3 : S_LEN - 1;
            Ua[0] = Ub[0]; Ua[1] = Ub[1];
            Ub[0] = *(const uint4*)&g_U[UADDR(tn * 128 + bx, 0)];
            Ub[1] = *(const uint4*)&g_U[UADDR(tn * 128 + bx, 1)];
        }
        __syncthreads();
    }

    #pragma unroll
    for (int r = 0; r < 2; ++r) {
        const int row = rowBase + g + 8 * r;
        #pragma unroll
        for (int nt = 0; nt < 2; ++nt)
            *(float2*)&out[(size_t)row * HID + colW + nt * 8 + tq * 2] =
                make_float2(h[r][nt][0], h[r][nt][1]);
    }
}

// ============================== launch =====================================

extern "C" void kernel_launch(void* const* d_in, const int* in_sizes, int n_in,
                              void* d_out, int out_size)
{
    const float* x   = (const float*)d_in[0];
    const float* h0  = (const float*)d_in[1];
    const float* Wih = (const float*)d_in[2];
    const float* bih = (const float*)d_in[3];
    const float* Whh = (const float*)d_in[4];
    const float* bhh = (const float*)d_in[5];

    cudaFuncSetAttribute(precompute_kernel,
                         cudaFuncAttributeMaxDynamicSharedMemorySize, P2_SMEM);
    precompute_kernel<<<P2_GRID, P2_THREADS, P2_SMEM>>>(x, Wih, bih);

    cudaFuncSetAttribute(loop_kernel,
                         cudaFuncAttributeMaxDynamicSharedMemorySize, L_SMEM);
    loop_kernel<<<BATCH / 16, L_THREADS, L_SMEM>>>(h0, bhh, Whh, (float*)d_out);
}

// round 17
// speedup vs baseline: 1.8609x; 1.4571x over previous
#include <cuda_runtime.h>
#include <cuda_fp16.h>
#include <cstdint>

#define S_LEN 512
#define BATCH 2048
#define DIN 64
#define HID 128
#define NROWS (S_LEN * BATCH)

// U scratch, single packed fp16 pairs:
// u32 index = bi*1024 + lw*128 + lane*4 + r*2 + nt
__device__ uint32_t g_U[(size_t)NROWS * HID / 2];

__device__ __forceinline__ float fast_tanh(float v) {
    float r;
    asm("tanh.approx.f32 %0, %1;" : "=f"(r) : "f"(v));
    return r;
}
__device__ __forceinline__ void ldsm4(uint32_t r[4], uint32_t addr) {
    asm volatile("ldmatrix.sync.aligned.m8n8.x4.shared.b16 {%0,%1,%2,%3}, [%4];"
                 : "=r"(r[0]), "=r"(r[1]), "=r"(r[2]), "=r"(r[3]) : "r"(addr));
}
__device__ __forceinline__ void mma_f16(float d[4], const uint32_t a[4],
                                        const uint32_t b0, const uint32_t b1) {
    asm volatile("mma.sync.aligned.m16n8k16.row.col.f32.f16.f16.f32 "
                 "{%0,%1,%2,%3}, {%4,%5,%6,%7}, {%8,%9}, {%0,%1,%2,%3};"
                 : "+f"(d[0]), "+f"(d[1]), "+f"(d[2]), "+f"(d[3])
                 : "r"(a[0]), "r"(a[1]), "r"(a[2]), "r"(a[3]), "r"(b0), "r"(b1));
}
__device__ __forceinline__ uint32_t smem_u32(const void* p) {
    uint32_t a;
    asm("{ .reg .u64 t; cvta.to.shared.u64 t, %1; cvt.u32.u64 %0, t; }"
        : "=r"(a) : "l"(p));
    return a;
}
__device__ __forceinline__ uint32_t cvt2h(float lo, float hi) {
    uint32_t r;
    asm("cvt.rn.f16x2.f32 %0, %1, %2;" : "=r"(r) : "f"(hi), "f"(lo));
    return r;
}
__device__ __forceinline__ float2 uh2(uint32_t p) {
    __half2 h = *(__half2*)&p;
    return __half22float2(h);
}

// ============ Kernel 1: U = x @ W_ih^T + b_ih via fp16 mma (1 product) =====

#define P2_THREADS 256
#define P2_GRID 592
#define NTILES (NROWS / 32)
#define PROW 144
#define PWSPL (HID * PROW)          // 18432 single W_ih plane
#define PXSPL (32 * PROW)           // 4608 single x plane
#define PW 0
#define PX PWSPL
#define P2_SMEM (PX + 2 * PXSPL)    // 27648

__global__ void __launch_bounds__(P2_THREADS)
precompute_kernel(const float* __restrict__ x, const float* __restrict__ Wih,
                  const float* __restrict__ bih)
{
    extern __shared__ unsigned char sm[];
    const uint32_t smem_b = smem_u32(sm);

    const int tid  = threadIdx.x;
    const int warp = tid >> 5;
    const int lane = tid & 31;
    const int tq   = lane & 3;
    const int rg   = warp >> 2;
    const int pwc  = warp & 3;
    const int colWp = pwc * 32;

    // ---- stage W_ih single fp16 plane (once) ----
    for (int idx = tid; idx < HID * DIN; idx += P2_THREADS) {
        const int n = idx >> 6, k = idx & 63;
        *(__half*)(sm + PW + (size_t)n * PROW + (size_t)k * 2) =
            __float2half_rn(Wih[idx]);
    }

    float bi0[4], bi1[4];
    #pragma unroll
    for (int nt = 0; nt < 4; ++nt) {
        bi0[nt] = bih[colWp + nt * 8 + tq * 2];
        bi1[nt] = bih[colWp + nt * 8 + tq * 2 + 1];
    }

    const int q  = lane >> 3;
    const int lr = lane & 7;
    const uint32_t xa_lane = (uint32_t)((rg * 16 + lr + (q & 1) * 8) * PROW +
                                        ((q & 2) ? 8 : 0) * 2);
    const uint32_t wb = smem_b + PW +
        (uint32_t)((colWp + lr + ((q & 2) ? 8 : 0)) * PROW + ((q & 1) ? 8 : 0) * 2);

    const int sr = tid >> 3;
    const int sc = (tid & 7) * 8;

    // ---- prologue: load x for first tile ----
    int blk = blockIdx.x;
    float4 v0, v1;
    if (blk < NTILES) {
        const float* p = x + ((size_t)blk * 32 + sr) * DIN + sc;
        v0 = *(const float4*)p; v1 = *(const float4*)(p + 4);
    }
    int cur = 0;
    __syncthreads();

    while (blk < NTILES) {
        // ---- stage x tile (single fp16 plane): 1x STS.128 per thread ----
        {
            uint4 o;
            o.x = cvt2h(v0.x, v0.y);
            o.y = cvt2h(v0.z, v0.w);
            o.z = cvt2h(v1.x, v1.y);
            o.w = cvt2h(v1.z, v1.w);
            *(uint4*)(sm + PX + cur * PXSPL + sr * PROW + sc * 2) = o;
        }
        __syncthreads();

        // ---- prefetch next tile ----
        const int nblk = blk + P2_GRID;
        if (nblk < NTILES) {
            const float* p = x + ((size_t)nblk * 32 + sr) * DIN + sc;
            v0 = *(const float4*)p; v1 = *(const float4*)(p + 4);
        }

        // ---- mma: 1 product ----
        float D[4][4];
        #pragma unroll
        for (int nt = 0; nt < 4; ++nt) {
            D[nt][0] = bi0[nt]; D[nt][1] = bi1[nt];
            D[nt][2] = bi0[nt]; D[nt][3] = bi1[nt];
        }
        const uint32_t xa = smem_b + PX + (uint32_t)cur * PXSPL + xa_lane;
        #pragma unroll
        for (int ks = 0; ks < 4; ++ks) {
            uint32_t A0[4];
            ldsm4(A0, xa + ks * 32);
            #pragma unroll
            for (int np = 0; np < 2; ++np) {
                uint32_t B0[4];
                ldsm4(B0, wb + (uint32_t)(np * 16 * PROW) + ks * 32);
                #pragma unroll
                for (int hf = 0; hf < 2; ++hf)
                    mma_f16(D[np * 2 + hf], A0, B0[2 * hf], B0[2 * hf + 1]);
            }
        }

        // ---- write U: packed fp16, 2x dense STG.128 per lane ----
        const size_t biBlk = ((size_t)blk * 32 >> 4) + rg;
        #pragma unroll
        for (int lwh = 0; lwh < 2; ++lwh) {
            const int lw  = pwc * 2 + lwh;
            const int nt0 = lwh * 2, nt1 = lwh * 2 + 1;
            uint4 o;
            o.x = cvt2h(D[nt0][0], D[nt0][1]);   // r0, nt0
            o.y = cvt2h(D[nt1][0], D[nt1][1]);   // r0, nt1
            o.z = cvt2h(D[nt0][2], D[nt0][3]);   // r1, nt0
            o.w = cvt2h(D[nt1][2], D[nt1][3]);   // r1, nt1
            *(uint4*)&g_U[biBlk * 1024 + (size_t)lw * 128 + lane * 4] = o;
        }

        blk = nblk;
        cur ^= 1;
    }
}

// ====== Kernel 2: recurrence, fp16 1-product GEMM2, 4 mma chains ==========

#define ROWB 272
#define WSPL (HID * ROWB)           // 34816 single W_hh plane
#define ASPL (16 * ROWB)            // 4352 single a plane
#define SM_W 0
#define SM_A WSPL
#define L_SMEM (SM_A + 2 * ASPL)    // 43520
#define L_THREADS 256

__global__ void __launch_bounds__(L_THREADS, 1)
loop_kernel(const float* __restrict__ h0, const float* __restrict__ bhh,
            const float* __restrict__ Whh, float* __restrict__ out)
{
    extern __shared__ unsigned char smem[];
    const uint32_t smem_b = smem_u32(smem);

    const int tid  = threadIdx.x;
    const int warp = tid >> 5;
    const int lane = tid & 31;
    const int g    = lane >> 2;
    const int tq   = lane & 3;
    const int bx   = blockIdx.x;
    const int rowBase = bx * 16;
    const int colW = warp * 16;

    // ---- stage W_hh single fp16 plane ----
    for (int idx = tid; idx < HID * HID; idx += L_THREADS) {
        const int n = idx >> 7, k = idx & 127;
        *(__half*)(smem + SM_W + (size_t)n * ROWB + (size_t)k * 2) =
            __float2half_rn(Whh[idx]);
    }

    float bh0[2], bh1[2];
    #pragma unroll
    for (int nt = 0; nt < 2; ++nt) {
        bh0[nt] = bhh[colW + nt * 8 + tq * 2];
        bh1[nt] = bhh[colW + nt * 8 + tq * 2 + 1];
    }

    // packed-fp16 U address: uint4 per (bi) per lane
    #define UADDR(bi) ((size_t)(bi) * 1024 + (size_t)warp * 128 + lane * 4)

    // ---- h, a registers; stage a(0) ----
    float h[2][2][2], a[2][2][2];
    {
        uint4 u = *(const uint4*)&g_U[UADDR(bx)];
        const uint32_t uw[4] = {u.x, u.y, u.z, u.w};
        #pragma unroll
        for (int r = 0; r < 2; ++r) {
            const int row = rowBase + g + 8 * r;
            #pragma unroll
            for (int nt = 0; nt < 2; ++nt) {
                float2 hv = *(const float2*)&h0[(size_t)row * HID + colW + nt * 8 + tq * 2];
                h[r][nt][0] = hv.x; h[r][nt][1] = hv.y;
                float2 uf = uh2(uw[r * 2 + nt]);
                a[r][nt][0] = uf.x * hv.x;
                a[r][nt][1] = uf.y * hv.y;
            }
        }
    }
    #pragma unroll
    for (int r = 0; r < 2; ++r) {
        const int lrow = g + 8 * r;
        #pragma unroll
        for (int nt = 0; nt < 2; ++nt) {
            const size_t o = (size_t)lrow * ROWB + (size_t)(colW + nt * 8 + tq * 2) * 2;
            *(uint32_t*)(smem + SM_A + o) = cvt2h(a[r][nt][0], a[r][nt][1]);
        }
    }

    // ---- 2-deep U prefetch ----
    uint4 Ua = *(const uint4*)&g_U[UADDR(128 + bx)];
    uint4 Ub = *(const uint4*)&g_U[UADDR(256 + bx)];
    __syncthreads();

    const int q  = lane >> 3;
    const int lr = lane & 7;
    const uint32_t a_off = (uint32_t)((lr + (q & 1) * 8) * ROWB + ((q & 2) ? 8 : 0) * 2);
    const uint32_t b_off = smem_b + SM_W +
        (uint32_t)((colW + lr + ((q & 2) ? 8 : 0)) * ROWB + ((q & 1) ? 8 : 0) * 2);

    // ---- preload W_hh B-fragments (loop-invariant) ----
    uint32_t Bf0[8][4];
    #pragma unroll
    for (int ks = 0; ks < 8; ++ks)
        ldsm4(Bf0[ks], b_off + ks * 32);

    const uint32_t abase = smem_b + SM_A;

    for (int t = 0; t < S_LEN; ++t) {
        const int buf = t & 1;

        // ---- hoisted U(t+1) unpack ----
        float Uf[2][2][2];
        {
            const uint32_t uw[4] = {Ua.x, Ua.y, Ua.z, Ua.w};
            #pragma unroll
            for (int r = 0; r < 2; ++r)
                #pragma unroll
                for (int nt = 0; nt < 2; ++nt) {
                    float2 f = uh2(uw[r * 2 + nt]);
                    Uf[r][nt][0] = f.x; Uf[r][nt][1] = f.y;
                }
        }

        // ---- mma: 1 product x 2 ks-parities x 2 nt = 4 chains of depth 4
        float D0[2][2][4];
        #pragma unroll
        for (int nt = 0; nt < 2; ++nt) {
            D0[0][nt][0] = bh0[nt]; D0[0][nt][1] = bh1[nt];
            D0[0][nt][2] = bh0[nt]; D0[0][nt][3] = bh1[nt];
            #pragma unroll
            for (int e = 0; e < 4; ++e) D0[1][nt][e] = 0.0f;
        }

        const uint32_t abuf = abase + (uint32_t)buf * ASPL + a_off;
        #pragma unroll
        for (int ks = 0; ks < 8; ++ks) {
            const int par = ks & 1;
            uint32_t A0[4];
            ldsm4(A0, abuf + ks * 32);
            #pragma unroll
            for (int nt = 0; nt < 2; ++nt)
                mma_f16(D0[par][nt], A0, Bf0[ks][2 * nt], Bf0[ks][2 * nt + 1]);
        }

        // ---- epilogue ----
        #pragma unroll
        for (int r = 0; r < 2; ++r) {
            const int lrow = g + 8 * r;
            #pragma unroll
            for (int nt = 0; nt < 2; ++nt) {
                float P0 = D0[0][nt][2 * r]     + D0[1][nt][2 * r];
                float P1 = D0[0][nt][2 * r + 1] + D0[1][nt][2 * r + 1];
                float h0n = fast_tanh(fmaf(P0, h[r][nt][0], a[r][nt][0]));
                float h1n = fast_tanh(fmaf(P1, h[r][nt][1], a[r][nt][1]));
                h[r][nt][0] = h0n; h[r][nt][1] = h1n;
                float v0 = Uf[r][nt][0] * h0n;
                float v1 = Uf[r][nt][1] * h1n;
                a[r][nt][0] = v0; a[r][nt][1] = v1;

                const size_t o = (size_t)(buf ^ 1) * ASPL + (size_t)lrow * ROWB +
                                 (size_t)(colW + nt * 8 + tq * 2) * 2;
                *(uint32_t*)(smem + SM_A + o) = cvt2h(v0, v1);
            }
        }

        // ---- shift prefetch: Ua <- Ub, issue Ub = U(t+3) ----
        {
            const int tn = (t + 3 < S_LEN) ? t + 3 : S_LEN - 1;
            Ua = Ub;
            Ub = *(const uint4*)&g_U[UADDR(tn * 128 + bx)];
        }
        __syncthreads();
    }

    #pragma unroll
    for (int r = 0; r < 2; ++r) {
        const int row = rowBase + g + 8 * r;
        #pragma unroll
        for (int nt = 0; nt < 2; ++nt)
            *(float2*)&out[(size_t)row * HID + colW + nt * 8 + tq * 2] =
                make_float2(h[r][nt][0], h[r][nt][1]);
    }
}

// ============================== launch =====================================

extern "C" void kernel_launch(void* const* d_in, const int* in_sizes, int n_in,
                              void* d_out, int out_size)
{
    const float* x   = (const float*)d_in[0];
    const float* h0  = (const float*)d_in[1];
    const float* Wih = (const float*)d_in[2];
    const float* bih = (const float*)d_in[3];
    const float* Whh = (const float*)d_in[4];
    const float* bhh = (const float*)d_in[5];

    cudaFuncSetAttribute(precompute_kernel,
                         cudaFuncAttributeMaxDynamicSharedMemorySize, P2_SMEM);
    precompute_kernel<<<P2_GRID, P2_THREADS, P2_SMEM>>>(x, Wih, bih);

    cudaFuncSetAttribute(loop_kernel,
                         cudaFuncAttributeMaxDynamicSharedMemorySize, L_SMEM);
    loop_kernel<<<BATCH / 16, L_THREADS, L_SMEM>>>(h0, bhh, Whh, (float*)d_out);
}